// round 5
// baseline (speedup 1.0000x reference)
#include <cuda_runtime.h>
#include <cstdint>

#define BATCH  16
#define MAXLEN 128
#define NTOK   (BATCH * MAXLEN)   // 2048
#define VOCAB  32128
#define V4     (VOCAB / 4)        // 8032
#define EMB    768

// Scratch (device globals: allocation-free, graph-capturable)
__device__ int g_hot[NTOK];
__device__ int g_rowa[NTOK];   // word-embedding row for inputs_embeds, -1 = zero
__device__ int g_rowb[NTOK];   // word-embedding row for psg_embeds,   -1 = zero

// ---------------------------------------------------------------------------
// Bit-exact replication of:
//   coord = jnp.linspace(-1, 1, size)[h]
//     JAX linspace (num>1): s = iota(f32 h)/f32(div); out = start*(1-s)+stop*s,
//     endpoint appended exactly as `stop`.
//   ix = ((coord + 1.0)*size - 1.0)/2.0 ;  round half-even ; clip [0, size-1]
// All ops forced to un-fused f32 (XLA emits separate rounded mul/add HLOs).
// ---------------------------------------------------------------------------
__device__ __forceinline__ int nearest_idx_rep(int h, int size) {
    float coord;
    if (h == size - 1) {
        coord = 1.0f;                                     // endpoint set to stop
    } else {
        float s = __fdiv_rn((float)h, (float)(size - 1)); // iota/div
        float t = __fsub_rn(1.0f, s);                     // (1 - step)
        float a = __fmul_rn(-1.0f, t);                    // start*(1-step)
        coord   = __fadd_rn(a, s);                        // + stop*step
    }
    float u1 = __fadd_rn(coord, 1.0f);
    float u2 = __fmul_rn(u1, (float)size);
    float u3 = __fsub_rn(u2, 1.0f);
    float ix = __fdiv_rn(u3, 2.0f);
    float r  = rintf(ix);                                 // round half-to-even
    r = fminf(fmaxf(r, 0.0f), (float)(size - 1));
    return (int)r;
}

// ---------------------------------------------------------------------------
// K1: first-occurrence argmax over V of (logits + gumbel), one block per token.
// Pure HBM stream: 526 MB total.
// ---------------------------------------------------------------------------
__global__ __launch_bounds__(256) void k_argmax(
    const float4* __restrict__ lg, const float4* __restrict__ gm)
{
    const int token = blockIdx.x;
    const float4* L = lg + (size_t)token * V4;
    const float4* G = gm + (size_t)token * V4;

    float best = -3.402823466e38f;
    int   bi   = 0;

    #pragma unroll 4
    for (int i = threadIdx.x; i < V4; i += 256) {
        float4 a = __ldg(&L[i]);
        float4 c = __ldg(&G[i]);
        float v0 = __fadd_rn(a.x, c.x);
        float v1 = __fadd_rn(a.y, c.y);
        float v2 = __fadd_rn(a.z, c.z);
        float v3 = __fadd_rn(a.w, c.w);
        int base = i << 2;
        // per-thread indices strictly increase -> '>' keeps first occurrence
        if (v0 > best) { best = v0; bi = base;     }
        if (v1 > best) { best = v1; bi = base + 1; }
        if (v2 > best) { best = v2; bi = base + 2; }
        if (v3 > best) { best = v3; bi = base + 3; }
    }

    // (maxval, min-index-on-tie) semilattice reduce == jnp.argmax semantics
    #pragma unroll
    for (int o = 16; o > 0; o >>= 1) {
        float ov = __shfl_down_sync(0xffffffffu, best, o);
        int   oi = __shfl_down_sync(0xffffffffu, bi,   o);
        if (ov > best || (ov == best && oi < bi)) { best = ov; bi = oi; }
    }

    __shared__ float sv[8];
    __shared__ int   si[8];
    int wid = threadIdx.x >> 5;
    if ((threadIdx.x & 31) == 0) { sv[wid] = best; si[wid] = bi; }
    __syncthreads();
    if (threadIdx.x == 0) {
        #pragma unroll
        for (int w = 1; w < 8; w++) {
            if (sv[w] > best || (sv[w] == best && si[w] < bi)) {
                best = sv[w]; bi = si[w];
            }
        }
        g_hot[token] = bi;
    }
}

// ---------------------------------------------------------------------------
// K2: per-batch passage bookkeeping + row_idx replication. One block per batch.
//   psg      = roll(psg_ids, 1) with BOS=1
//   extr[j]  = (1 - mask[L-1-j]) * psg[j]
//   trunc[j] = extr[(j - sum(mask)) mod L]
//   flag[j]  = any_{k<=j} trunc[k] != 0
// ---------------------------------------------------------------------------
__global__ __launch_bounds__(MAXLEN) void k_prep(
    const int* __restrict__ mask, const int* __restrict__ psg)
{
    const int b = blockIdx.x;
    const int j = threadIdx.x;

    __shared__ int s_mask[MAXLEN];
    __shared__ int s_extr[MAXLEN];
    __shared__ int s_red[4];

    int m  = mask[b * MAXLEN + j];
    int pj = (j == 0) ? 1 : psg[b * MAXLEN + j - 1];
    s_mask[j] = m;
    __syncthreads();

    int fm = 1 - s_mask[MAXLEN - 1 - j];
    s_extr[j] = fm * pj;

    unsigned wsum = __reduce_add_sync(0xffffffffu, (unsigned)m);
    if ((j & 31) == 0) s_red[j >> 5] = (int)wsum;
    __syncthreads();                       // covers s_extr and s_red

    int shifts = s_red[0] + s_red[1] + s_red[2] + s_red[3];
    int pos    = (j - shifts + MAXLEN) & (MAXLEN - 1);
    int trunc  = s_extr[pos];

    int key = (trunc != 0) ? j : MAXLEN;
    unsigned wmin = __reduce_min_sync(0xffffffffu, (unsigned)key);
    __syncthreads();
    if ((j & 31) == 0) s_red[j >> 5] = (int)wmin;
    __syncthreads();
    int firstnz = min(min(s_red[0], s_red[1]), min(s_red[2], s_red[3]));

    int tok = b * MAXLEN + j;
    g_rowb[tok] = (j >= firstnz) ? trunc : -1;

    int hot = g_hot[tok];
    g_rowa[tok] = m ? nearest_idx_rep(hot, VOCAB) : -1;
}

// ---------------------------------------------------------------------------
// K3: output assembly. One block per token, one thread per embed dim.
//   out[tok,e] = (rowa>=0 ? WE[rowa, colidx(e)] : 0)
//              + (rowb>=0 ? WE[rowb, colidx(e)] : 0)
// colidx replicates _nearest_idx over linspace(-1,1,EMB) (== identity, but
// computed exactly to match the reference's float path).
// ---------------------------------------------------------------------------
__global__ __launch_bounds__(EMB) void k_gather(
    const float* __restrict__ we, float* __restrict__ out)
{
    const int tok = blockIdx.x;
    const int e   = threadIdx.x;

    int ra = g_rowa[tok];
    int rb = g_rowb[tok];
    int col = nearest_idx_rep(e, EMB);

    float v = 0.0f;
    if (ra >= 0) v = __ldg(&we[(size_t)ra * EMB + col]);
    if (rb >= 0) v = __fadd_rn(v, __ldg(&we[(size_t)rb * EMB + col]));
    out[(size_t)tok * EMB + e] = v;
}

// ---------------------------------------------------------------------------
// Entry point. Inputs (metadata order):
//   0: logits           f32 [16,128,32128]
//   1: rwrt_attn_mask   i32 [16,128]
//   2: psg_input_ids    i32 [16,128]
//   3: word_embeddings  f32 [32128,768]
//   4: gumbel_noise     f32 [16,128,32128]
// Output: f32 [16,128,768]
// ---------------------------------------------------------------------------
extern "C" void kernel_launch(void* const* d_in, const int* in_sizes, int n_in,
                              void* d_out, int out_size)
{
    const float* logits = (const float*)d_in[0];
    const int*   mask   = (const int*)  d_in[1];
    const int*   psg    = (const int*)  d_in[2];
    const float* we     = (const float*)d_in[3];
    const float* gum    = (const float*)d_in[4];
    float*       out    = (float*)d_out;

    k_argmax<<<NTOK, 256>>>((const float4*)logits, (const float4*)gum);
    k_prep  <<<BATCH, MAXLEN>>>(mask, psg);
    k_gather<<<NTOK, EMB>>>(we, out);
}